// round 2
// baseline (speedup 1.0000x reference)
#include <cuda_runtime.h>
#include <math.h>

#define B_SZ    2
#define L_SEQ   2048
#define D_MODEL 768
#define D_INNER 1536
#define D_STATE 16
#define DT_RANK 48
#define NK      (DT_RANK + 2*D_STATE)   /* 80 */
#define M_ROWS  (B_SZ*L_SEQ)            /* 4096 */

// ---------------- scratch (static device globals; no allocation) ----------------
__device__ float g_xz  [M_ROWS * 2 * D_INNER];   // in-proj output: x = cols [0,1536), z = cols [1536,3072)
__device__ float g_xc  [2][M_ROWS * D_INNER];    // conv+silu output per branch (branch 1 in reversed coords)
__device__ float g_xd  [2][M_ROWS * NK];         // x_dbl per branch
__device__ float g_dt  [2][M_ROWS * D_INNER];    // softplus(dt) per branch
__device__ float g_y   [2][M_ROWS * D_INNER];    // scan outputs (both stored at ORIGINAL l positions)
__device__ float g_gbuf[M_ROWS * D_INNER];       // 0.5*silu(z)*(y_f+y_b)

__device__ __forceinline__ float siluf(float x) {
    return x / (1.f + __expf(-x));
}

// ---------------- generic NT GEMM: C[m,n] = act(sum_k A[m,k]*B[n,k] + bias[n]) ----------------
// ACT: 0 = none, 1 = softplus
template<int BM,int BN,int BK,int TM,int TN,int ACT>
__global__ void __launch_bounds__(256, 1)
gemm_nt(const float* __restrict__ A, int lda,
        const float* __restrict__ Bm, int ldb,
        const float* __restrict__ bias,
        float* __restrict__ C, int ldc,
        int M, int N, int K)
{
    constexpr int NT = (BM/TM)*(BN/TN);
    __shared__ float As[BK][BM];
    __shared__ float Bs[BK][BN];

    const int tid = threadIdx.x;
    const int tx  = tid % (BN/TN);
    const int ty  = tid / (BN/TN);
    const int rowBase = blockIdx.y*BM + ty*TM;
    const int colBase = blockIdx.x*BN + tx*TN;

    float acc[TM][TN];
    #pragma unroll
    for (int i = 0; i < TM; ++i)
        #pragma unroll
        for (int j = 0; j < TN; ++j)
            acc[i][j] = 0.f;

    for (int k0 = 0; k0 < K; k0 += BK) {
        // load A tile (M is always a multiple of BM here)
        #pragma unroll
        for (int i = tid; i < BM*BK; i += NT) {
            int r = i / BK, k = i % BK;
            int gr = blockIdx.y*BM + r;
            As[k][r] = A[(size_t)gr*lda + k0 + k];
        }
        // load B tile (guard N)
        #pragma unroll
        for (int i = tid; i < BN*BK; i += NT) {
            int r = i / BK, k = i % BK;
            int gn = blockIdx.x*BN + r;
            Bs[k][r] = (gn < N) ? Bm[(size_t)gn*ldb + k0 + k] : 0.f;
        }
        __syncthreads();

        #pragma unroll
        for (int k = 0; k < BK; ++k) {
            float a[TM], bf[TN];
            #pragma unroll
            for (int i = 0; i < TM; ++i) a[i]  = As[k][ty*TM + i];
            #pragma unroll
            for (int j = 0; j < TN; ++j) bf[j] = Bs[k][tx*TN + j];
            #pragma unroll
            for (int i = 0; i < TM; ++i)
                #pragma unroll
                for (int j = 0; j < TN; ++j)
                    acc[i][j] += a[i]*bf[j];
        }
        __syncthreads();
    }

    #pragma unroll
    for (int i = 0; i < TM; ++i) {
        #pragma unroll
        for (int j = 0; j < TN; ++j) {
            int n = colBase + j;
            if (n < N) {
                float v = acc[i][j];
                if (bias) v += bias[n];
                if (ACT == 1) {               // softplus
                    v = (v > 20.f) ? v : log1pf(expf(v));
                }
                C[(size_t)(rowBase + i)*ldc + n] = v;
            }
        }
    }
}

// ---------------- depthwise causal conv (4 taps) + bias + silu, both branches ----------------
// Branch 0 (fwd):     xc0[b,t,d] = silu(cb_f[d] + sum_j cw_f[d,j] * x[b, t-3+j, d])
// Branch 1 (bwd, reversed coords t): operates on x_rev[u] = x[b, L-1-u]
__global__ void conv_kernel(const float* __restrict__ cw_f, const float* __restrict__ cb_f,
                            const float* __restrict__ cw_b, const float* __restrict__ cb_b)
{
    int d = blockIdx.x*blockDim.x + threadIdx.x;   // 0..1535
    int m = blockIdx.y;                            // 0..4095
    int b = m >> 11, t = m & (L_SEQ-1);

    float w0 = cw_f[d*4+0], w1 = cw_f[d*4+1], w2 = cw_f[d*4+2], w3 = cw_f[d*4+3];
    float v0 = cw_b[d*4+0], v1 = cw_b[d*4+1], v2 = cw_b[d*4+2], v3 = cw_b[d*4+3];

    const float* xcol = g_xz + d;
    size_t rowb = (size_t)(b*L_SEQ) * (2*D_INNER);

    float accf = cb_f[d];
    float accb = cb_b[d];
    // forward taps: u = t-3 .. t
    if (t >= 3) accf += w0 * xcol[rowb + (size_t)(t-3)*(2*D_INNER)];
    if (t >= 2) accf += w1 * xcol[rowb + (size_t)(t-2)*(2*D_INNER)];
    if (t >= 1) accf += w2 * xcol[rowb + (size_t)(t-1)*(2*D_INNER)];
    accf += w3 * xcol[rowb + (size_t)t*(2*D_INNER)];
    // backward: x_rev[u] = x[L-1-u]; taps u = t-3 .. t
    if (t >= 3) accb += v0 * xcol[rowb + (size_t)(L_SEQ-1-(t-3))*(2*D_INNER)];
    if (t >= 2) accb += v1 * xcol[rowb + (size_t)(L_SEQ-1-(t-2))*(2*D_INNER)];
    if (t >= 1) accb += v2 * xcol[rowb + (size_t)(L_SEQ-1-(t-1))*(2*D_INNER)];
    accb += v3 * xcol[rowb + (size_t)(L_SEQ-1-t)*(2*D_INNER)];

    g_xc[0][(size_t)m*D_INNER + d] = siluf(accf);
    g_xc[1][(size_t)m*D_INNER + d] = siluf(accb);
}

// ---------------- selective scan, both branches via blockIdx.z ----------------
// Thread layout: half-warp = one (b, d) channel, lane n in [0,16) = state dim.
// Block covers 16 d-channels; grid = (D_INNER/16, B_SZ, 2).
__global__ void scan_kernel(const float* __restrict__ Alog_f, const float* __restrict__ Alog_b,
                            const float* __restrict__ Dp_f,  const float* __restrict__ Dp_b)
{
    const int br = blockIdx.z;
    const float* __restrict__ dtbuf = br ? g_dt[1] : g_dt[0];
    const float* __restrict__ xcbuf = br ? g_xc[1] : g_xc[0];
    const float* __restrict__ xdbuf = br ? g_xd[1] : g_xd[0];
    float*       __restrict__ ybuf  = br ? g_y[1]  : g_y[0];
    const float* __restrict__ Alog  = br ? Alog_b : Alog_f;
    const float* __restrict__ Dpp   = br ? Dp_b   : Dp_f;

    const int tid  = threadIdx.x;
    const int lane = tid & 31;
    const int warp = tid >> 5;
    const int n    = lane & 15;
    const int dloc = warp*2 + (lane >> 4);
    const int d    = blockIdx.x*16 + dloc;
    const int b    = blockIdx.y;

    const float Acoef = -__expf(Alog[d*D_STATE + n]);
    const float Dv    = Dpp[d];

    const float* dtp = dtbuf + (size_t)b*L_SEQ*D_INNER + d;
    const float* xcp = xcbuf + (size_t)b*L_SEQ*D_INNER + d;
    const float* Bp  = xdbuf + (size_t)b*L_SEQ*NK + DT_RANK + n;
    const float* Cp  = Bp + D_STATE;

    float h = 0.f;
    for (int t = 0; t < L_SEQ; ++t) {
        float dt = __ldg(dtp + (size_t)t*D_INNER);
        float xv = __ldg(xcp + (size_t)t*D_INNER);
        float Bv = __ldg(Bp  + (size_t)t*NK);
        float Cv = __ldg(Cp  + (size_t)t*NK);

        float dA = __expf(dt * Acoef);
        h = dA*h + (dt*xv)*Bv;

        float p = h * Cv;
        p += __shfl_xor_sync(0xffffffffu, p, 8);
        p += __shfl_xor_sync(0xffffffffu, p, 4);
        p += __shfl_xor_sync(0xffffffffu, p, 2);
        p += __shfl_xor_sync(0xffffffffu, p, 1);

        if (n == 0) {
            int lout = br ? (L_SEQ - 1 - t) : t;   // bwd branch lands at original position
            ybuf[((size_t)b*L_SEQ + lout)*D_INNER + d] = p + Dv*xv;
        }
    }
}

// ---------------- combine: g = 0.5 * silu(z) * (y_f + y_b) ----------------
__global__ void combine_kernel()
{
    int idx = blockIdx.x*blockDim.x + threadIdx.x;
    int m = idx / D_INNER;
    int d = idx - m*D_INNER;
    float z = g_xz[(size_t)m*(2*D_INNER) + D_INNER + d];
    float s = siluf(z);
    g_gbuf[idx] = 0.5f * s * (g_y[0][idx] + g_y[1][idx]);
}

// ---------------- host ----------------
extern "C" void kernel_launch(void* const* d_in, const int* in_sizes, int n_in,
                              void* d_out, int out_size)
{
    const float* hs       = (const float*)d_in[0];
    const float* W_in     = (const float*)d_in[1];
    const float* conv_w   = (const float*)d_in[2];
    const float* conv_b   = (const float*)d_in[3];
    const float* conv_w_b = (const float*)d_in[4];
    const float* conv_b_b = (const float*)d_in[5];
    const float* W_x      = (const float*)d_in[6];
    const float* W_x_b    = (const float*)d_in[7];
    const float* W_dt     = (const float*)d_in[8];
    const float* b_dt     = (const float*)d_in[9];
    const float* W_dt_b   = (const float*)d_in[10];
    const float* b_dt_b   = (const float*)d_in[11];
    const float* A_log    = (const float*)d_in[12];
    const float* A_b_log  = (const float*)d_in[13];
    const float* Dp       = (const float*)d_in[14];
    const float* Dp_b     = (const float*)d_in[15];
    const float* W_out    = (const float*)d_in[16];
    float* out = (float*)d_out;

    static float *xz = nullptr, *xc = nullptr, *xd = nullptr, *dt = nullptr, *gb = nullptr;
    if (!xz) {
        cudaGetSymbolAddress((void**)&xz, g_xz);
        cudaGetSymbolAddress((void**)&xc, g_xc);
        cudaGetSymbolAddress((void**)&xd, g_xd);
        cudaGetSymbolAddress((void**)&dt, g_dt);
        cudaGetSymbolAddress((void**)&gb, g_gbuf);
    }
    float* xc0 = xc;                    float* xc1 = xc + (size_t)M_ROWS*D_INNER;
    float* xd0 = xd;                    float* xd1 = xd + (size_t)M_ROWS*NK;
    float* dt0 = dt;                    float* dt1 = dt + (size_t)M_ROWS*D_INNER;

    // 1) in-proj: xz[m, 0:3072] = hs[m, :] @ W_in^T     (M=4096, N=3072, K=768)
    gemm_nt<128,128,8,8,8,0><<<dim3(3072/128, M_ROWS/128), 256>>>(
        hs, D_MODEL, W_in, D_MODEL, nullptr, xz, 2*D_INNER, M_ROWS, 2*D_INNER, D_MODEL);

    // 2) conv + silu (both branches)
    conv_kernel<<<dim3(D_INNER/256, M_ROWS), 256>>>(conv_w, conv_b, conv_w_b, conv_b_b);

    // 3) x_dbl per branch: (M=4096, N=80, K=1536)
    gemm_nt<64,32,16,4,2,0><<<dim3((NK+31)/32, M_ROWS/64), 256>>>(
        xc0, D_INNER, W_x,   D_INNER, nullptr, xd0, NK, M_ROWS, NK, D_INNER);
    gemm_nt<64,32,16,4,2,0><<<dim3((NK+31)/32, M_ROWS/64), 256>>>(
        xc1, D_INNER, W_x_b, D_INNER, nullptr, xd1, NK, M_ROWS, NK, D_INNER);

    // 4) dt per branch: softplus(dt_lo @ W_dt^T + b_dt)  (M=4096, N=1536, K=48, lda=80)
    gemm_nt<128,128,8,8,8,1><<<dim3(D_INNER/128, M_ROWS/128), 256>>>(
        xd0, NK, W_dt,   DT_RANK, b_dt,   dt0, D_INNER, M_ROWS, D_INNER, DT_RANK);
    gemm_nt<128,128,8,8,8,1><<<dim3(D_INNER/128, M_ROWS/128), 256>>>(
        xd1, NK, W_dt_b, DT_RANK, b_dt_b, dt1, D_INNER, M_ROWS, D_INNER, DT_RANK);

    // 5) selective scan, both branches
    scan_kernel<<<dim3(D_INNER/16, B_SZ, 2), 256>>>(A_log, A_b_log, Dp, Dp_b);

    // 6) combine with gate
    combine_kernel<<<(M_ROWS*D_INNER)/256, 256>>>();

    // 7) out-proj: out = g @ W_out^T   (M=4096, N=768, K=1536)
    gemm_nt<128,128,8,8,8,0><<<dim3(D_MODEL/128, M_ROWS/128), 256>>>(
        gb, D_INNER, W_out, D_INNER, nullptr, out, D_MODEL, M_ROWS, D_MODEL, D_INNER);
}

// round 3
// speedup vs baseline: 1.3959x; 1.3959x over previous
#include <cuda_runtime.h>
#include <math.h>
#include <stdint.h>

#define B_SZ    2
#define L_SEQ   2048
#define D_MODEL 768
#define D_INNER 1536
#define D_STATE 16
#define DT_RANK 48
#define NK      (DT_RANK + 2*D_STATE)   /* 80 */
#define M_ROWS  (B_SZ*L_SEQ)            /* 4096 */

// ---------------- scratch (static device globals; no allocation) ----------------
__device__ float g_xz  [M_ROWS * 2 * D_INNER];
__device__ float g_xc  [2][M_ROWS * D_INNER];
__device__ float g_xd  [2][M_ROWS * NK];
__device__ float g_dt  [2][M_ROWS * D_INNER];
__device__ float g_y   [2][M_ROWS * D_INNER];
__device__ float g_gbuf[M_ROWS * D_INNER];

__device__ __forceinline__ float siluf(float x) {
    return x / (1.f + __expf(-x));
}

__device__ __forceinline__ uint32_t f2tf32(float x) {
    uint32_t r;
    asm("cvt.rna.tf32.f32 %0, %1;" : "=r"(r) : "f"(x));
    return r;
}

__device__ __forceinline__ void mma_tf32(float& c0, float& c1, float& c2, float& c3,
                                         uint32_t a0, uint32_t a1, uint32_t a2, uint32_t a3,
                                         uint32_t b0, uint32_t b1) {
    asm volatile("mma.sync.aligned.m16n8k8.row.col.f32.tf32.tf32.f32 "
                 "{%0,%1,%2,%3},{%4,%5,%6,%7},{%8,%9},{%0,%1,%2,%3};"
                 : "+f"(c0), "+f"(c1), "+f"(c2), "+f"(c3)
                 : "r"(a0), "r"(a1), "r"(a2), "r"(a3), "r"(b0), "r"(b1));
}

// =====================================================================
// 3xTF32 tensor-core NT GEMM: C[m,n] = act(sum_k A[m,k]*B[n,k] + bias[n])
// BM=BN=128, BK=16. 8 warps (wm 0..1, wn 0..3), warp tile 64x32.
// Requires: M % 128 == 0, K % 16 == 0, lda/ldb divisible by 4 (float4).
// N guarded. ACT: 0=none, 1=softplus.
// =====================================================================
#define SROW 20   /* 16 + pad 4; 20 % 32 makes (20*g + tig) distinct over lanes */

template<int ACT>
__global__ void __launch_bounds__(256, 1)
gemm_tf32x3(const float* __restrict__ A, int lda,
            const float* __restrict__ B, int ldb,
            const float* __restrict__ bias,
            float* __restrict__ C, int ldc,
            int N, int K)
{
    __shared__ float As[128][SROW];
    __shared__ float Bs[128][SROW];

    const int tid  = threadIdx.x;
    const int lane = tid & 31;
    const int g    = lane >> 2;     // 0..7
    const int tg   = lane & 3;      // 0..3
    const int warp = tid >> 5;
    const int wm   = warp & 1;      // 0..1
    const int wn   = warp >> 1;     // 0..3

    const int blockRow = blockIdx.y * 128;
    const int blockCol = blockIdx.x * 128;

    // fill mapping: q = tid&3 selects float4 within BK, r = tid>>2 selects row (0..63, +64)
    const int fq = tid & 3;
    const int fr = tid >> 2;

    float4 pa[2], pb[2];

    const int ktiles = K / 16;

    // ---- prefetch tile 0 into regs ----
    {
        const float* Ap = A + (size_t)(blockRow + fr) * lda + fq * 4;
        pa[0] = *(const float4*)(Ap);
        pa[1] = *(const float4*)(Ap + (size_t)64 * lda);
        int n0 = blockCol + fr, n1 = n0 + 64;
        pb[0] = (n0 < N) ? *(const float4*)(B + (size_t)n0 * ldb + fq * 4) : make_float4(0.f,0.f,0.f,0.f);
        pb[1] = (n1 < N) ? *(const float4*)(B + (size_t)n1 * ldb + fq * 4) : make_float4(0.f,0.f,0.f,0.f);
    }

    float acc[4][4][4];
    #pragma unroll
    for (int i = 0; i < 4; ++i)
        #pragma unroll
        for (int j = 0; j < 4; ++j)
            #pragma unroll
            for (int r = 0; r < 4; ++r)
                acc[i][j][r] = 0.f;

    const int mwbase = wm * 64;
    const int nwbase = wn * 32;

    for (int kt = 0; kt < ktiles; ++kt) {
        // store prefetched regs to smem
        *(float4*)&As[fr     ][fq*4] = pa[0];
        *(float4*)&As[fr + 64][fq*4] = pa[1];
        *(float4*)&Bs[fr     ][fq*4] = pb[0];
        *(float4*)&Bs[fr + 64][fq*4] = pb[1];
        __syncthreads();

        // prefetch next tile
        if (kt + 1 < ktiles) {
            int k0 = (kt + 1) * 16;
            const float* Ap = A + (size_t)(blockRow + fr) * lda + k0 + fq * 4;
            pa[0] = *(const float4*)(Ap);
            pa[1] = *(const float4*)(Ap + (size_t)64 * lda);
            int n0 = blockCol + fr, n1 = n0 + 64;
            pb[0] = (n0 < N) ? *(const float4*)(B + (size_t)n0 * ldb + k0 + fq * 4) : make_float4(0.f,0.f,0.f,0.f);
            pb[1] = (n1 < N) ? *(const float4*)(B + (size_t)n1 * ldb + k0 + fq * 4) : make_float4(0.f,0.f,0.f,0.f);
        }

        // compute on the tile: two k8 steps
        #pragma unroll
        for (int s = 0; s < 2; ++s) {
            const int kb = s * 8;
            uint32_t bh[4][2], bl[4][2];
            #pragma unroll
            for (int j = 0; j < 4; ++j) {
                float b0 = Bs[nwbase + j*8 + g][kb + tg];
                float b1 = Bs[nwbase + j*8 + g][kb + tg + 4];
                bh[j][0] = f2tf32(b0); bl[j][0] = f2tf32(b0 - __uint_as_float(bh[j][0]));
                bh[j][1] = f2tf32(b1); bl[j][1] = f2tf32(b1 - __uint_as_float(bh[j][1]));
            }
            #pragma unroll
            for (int i = 0; i < 4; ++i) {
                const int mb = mwbase + i * 16;
                float a0 = As[mb + g    ][kb + tg];
                float a1 = As[mb + g + 8][kb + tg];
                float a2 = As[mb + g    ][kb + tg + 4];
                float a3 = As[mb + g + 8][kb + tg + 4];
                uint32_t ah0 = f2tf32(a0), ah1 = f2tf32(a1), ah2 = f2tf32(a2), ah3 = f2tf32(a3);
                uint32_t al0 = f2tf32(a0 - __uint_as_float(ah0));
                uint32_t al1 = f2tf32(a1 - __uint_as_float(ah1));
                uint32_t al2 = f2tf32(a2 - __uint_as_float(ah2));
                uint32_t al3 = f2tf32(a3 - __uint_as_float(ah3));
                #pragma unroll
                for (int j = 0; j < 4; ++j) {
                    mma_tf32(acc[i][j][0], acc[i][j][1], acc[i][j][2], acc[i][j][3],
                             ah0, ah1, ah2, ah3, bh[j][0], bh[j][1]);
                    mma_tf32(acc[i][j][0], acc[i][j][1], acc[i][j][2], acc[i][j][3],
                             ah0, ah1, ah2, ah3, bl[j][0], bl[j][1]);
                    mma_tf32(acc[i][j][0], acc[i][j][1], acc[i][j][2], acc[i][j][3],
                             al0, al1, al2, al3, bh[j][0], bh[j][1]);
                }
            }
        }
        __syncthreads();
    }

    // ---- epilogue ----
    #pragma unroll
    for (int i = 0; i < 4; ++i) {
        int r0 = blockRow + mwbase + i*16 + g;
        int r1 = r0 + 8;
        #pragma unroll
        for (int j = 0; j < 4; ++j) {
            int c0 = blockCol + nwbase + j*8 + 2*tg;
            #pragma unroll
            for (int h = 0; h < 2; ++h) {
                int cc = c0 + h;
                if (cc < N) {
                    float v0 = acc[i][j][0 + h];
                    float v1 = acc[i][j][2 + h];
                    if (ACT == 1) {
                        float bv = bias[cc];
                        v0 += bv; v1 += bv;
                        v0 = (v0 > 20.f) ? v0 : log1pf(expf(v0));
                        v1 = (v1 > 20.f) ? v1 : log1pf(expf(v1));
                    }
                    C[(size_t)r0 * ldc + cc] = v0;
                    C[(size_t)r1 * ldc + cc] = v1;
                }
            }
        }
    }
}

// ---------------- depthwise causal conv (4 taps) + bias + silu, both branches ----------------
__global__ void conv_kernel(const float* __restrict__ cw_f, const float* __restrict__ cb_f,
                            const float* __restrict__ cw_b, const float* __restrict__ cb_b)
{
    int d = blockIdx.x*blockDim.x + threadIdx.x;   // 0..1535
    int m = blockIdx.y;                            // 0..4095
    int b = m >> 11, t = m & (L_SEQ-1);

    float w0 = cw_f[d*4+0], w1 = cw_f[d*4+1], w2 = cw_f[d*4+2], w3 = cw_f[d*4+3];
    float v0 = cw_b[d*4+0], v1 = cw_b[d*4+1], v2 = cw_b[d*4+2], v3 = cw_b[d*4+3];

    const float* xcol = g_xz + d;
    size_t rowb = (size_t)(b*L_SEQ) * (2*D_INNER);

    float accf = cb_f[d];
    float accb = cb_b[d];
    if (t >= 3) accf += w0 * xcol[rowb + (size_t)(t-3)*(2*D_INNER)];
    if (t >= 2) accf += w1 * xcol[rowb + (size_t)(t-2)*(2*D_INNER)];
    if (t >= 1) accf += w2 * xcol[rowb + (size_t)(t-1)*(2*D_INNER)];
    accf += w3 * xcol[rowb + (size_t)t*(2*D_INNER)];
    if (t >= 3) accb += v0 * xcol[rowb + (size_t)(L_SEQ-1-(t-3))*(2*D_INNER)];
    if (t >= 2) accb += v1 * xcol[rowb + (size_t)(L_SEQ-1-(t-2))*(2*D_INNER)];
    if (t >= 1) accb += v2 * xcol[rowb + (size_t)(L_SEQ-1-(t-1))*(2*D_INNER)];
    accb += v3 * xcol[rowb + (size_t)(L_SEQ-1-t)*(2*D_INNER)];

    g_xc[0][(size_t)m*D_INNER + d] = siluf(accf);
    g_xc[1][(size_t)m*D_INNER + d] = siluf(accb);
}

// ---------------- selective scan, both branches via blockIdx.z ----------------
__global__ void scan_kernel(const float* __restrict__ Alog_f, const float* __restrict__ Alog_b,
                            const float* __restrict__ Dp_f,  const float* __restrict__ Dp_b)
{
    const int br = blockIdx.z;
    const float* __restrict__ dtbuf = br ? g_dt[1] : g_dt[0];
    const float* __restrict__ xcbuf = br ? g_xc[1] : g_xc[0];
    const float* __restrict__ xdbuf = br ? g_xd[1] : g_xd[0];
    float*       __restrict__ ybuf  = br ? g_y[1]  : g_y[0];
    const float* __restrict__ Alog  = br ? Alog_b : Alog_f;
    const float* __restrict__ Dpp   = br ? Dp_b   : Dp_f;

    const int tid  = threadIdx.x;
    const int lane = tid & 31;
    const int warp = tid >> 5;
    const int n    = lane & 15;
    const int dloc = warp*2 + (lane >> 4);
    const int d    = blockIdx.x*16 + dloc;
    const int b    = blockIdx.y;

    const float Acoef = -__expf(Alog[d*D_STATE + n]);
    const float Dv    = Dpp[d];

    const float* dtp = dtbuf + (size_t)b*L_SEQ*D_INNER + d;
    const float* xcp = xcbuf + (size_t)b*L_SEQ*D_INNER + d;
    const float* Bp  = xdbuf + (size_t)b*L_SEQ*NK + DT_RANK + n;
    const float* Cp  = Bp + D_STATE;

    float h = 0.f;
    for (int t = 0; t < L_SEQ; ++t) {
        float dt = __ldg(dtp + (size_t)t*D_INNER);
        float xv = __ldg(xcp + (size_t)t*D_INNER);
        float Bv = __ldg(Bp  + (size_t)t*NK);
        float Cv = __ldg(Cp  + (size_t)t*NK);

        float dA = __expf(dt * Acoef);
        h = dA*h + (dt*xv)*Bv;

        float p = h * Cv;
        p += __shfl_xor_sync(0xffffffffu, p, 8);
        p += __shfl_xor_sync(0xffffffffu, p, 4);
        p += __shfl_xor_sync(0xffffffffu, p, 2);
        p += __shfl_xor_sync(0xffffffffu, p, 1);

        if (n == 0) {
            int lout = br ? (L_SEQ - 1 - t) : t;
            ybuf[((size_t)b*L_SEQ + lout)*D_INNER + d] = p + Dv*xv;
        }
    }
}

// ---------------- combine: g = 0.5 * silu(z) * (y_f + y_b) ----------------
__global__ void combine_kernel()
{
    int idx = blockIdx.x*blockDim.x + threadIdx.x;
    int m = idx / D_INNER;
    int d = idx - m*D_INNER;
    float z = g_xz[(size_t)m*(2*D_INNER) + D_INNER + d];
    float s = siluf(z);
    g_gbuf[idx] = 0.5f * s * (g_y[0][idx] + g_y[1][idx]);
}

// ---------------- host ----------------
extern "C" void kernel_launch(void* const* d_in, const int* in_sizes, int n_in,
                              void* d_out, int out_size)
{
    const float* hs       = (const float*)d_in[0];
    const float* W_in     = (const float*)d_in[1];
    const float* conv_w   = (const float*)d_in[2];
    const float* conv_b   = (const float*)d_in[3];
    const float* conv_w_b = (const float*)d_in[4];
    const float* conv_b_b = (const float*)d_in[5];
    const float* W_x      = (const float*)d_in[6];
    const float* W_x_b    = (const float*)d_in[7];
    const float* W_dt     = (const float*)d_in[8];
    const float* b_dt     = (const float*)d_in[9];
    const float* W_dt_b   = (const float*)d_in[10];
    const float* b_dt_b   = (const float*)d_in[11];
    const float* A_log    = (const float*)d_in[12];
    const float* A_b_log  = (const float*)d_in[13];
    const float* Dp       = (const float*)d_in[14];
    const float* Dp_b     = (const float*)d_in[15];
    const float* W_out    = (const float*)d_in[16];
    float* out = (float*)d_out;

    static float *xz = nullptr, *xc = nullptr, *xd = nullptr, *dt = nullptr, *gb = nullptr;
    if (!xz) {
        cudaGetSymbolAddress((void**)&xz, g_xz);
        cudaGetSymbolAddress((void**)&xc, g_xc);
        cudaGetSymbolAddress((void**)&xd, g_xd);
        cudaGetSymbolAddress((void**)&dt, g_dt);
        cudaGetSymbolAddress((void**)&gb, g_gbuf);
    }
    float* xc0 = xc;                    float* xc1 = xc + (size_t)M_ROWS*D_INNER;
    float* xd0 = xd;                    float* xd1 = xd + (size_t)M_ROWS*NK;
    float* dt0 = dt;                    float* dt1 = dt + (size_t)M_ROWS*D_INNER;

    // 1) in-proj: (M=4096, N=3072, K=768)
    gemm_tf32x3<0><<<dim3(3072/128, M_ROWS/128), 256>>>(
        hs, D_MODEL, W_in, D_MODEL, nullptr, xz, 2*D_INNER, 2*D_INNER, D_MODEL);

    // 2) conv + silu (both branches)
    conv_kernel<<<dim3(D_INNER/256, M_ROWS), 256>>>(conv_w, conv_b, conv_w_b, conv_b_b);

    // 3) x_dbl per branch: (M=4096, N=80, K=1536)
    gemm_tf32x3<0><<<dim3(1, M_ROWS/128), 256>>>(
        xc0, D_INNER, W_x,   D_INNER, nullptr, xd0, NK, NK, D_INNER);
    gemm_tf32x3<0><<<dim3(1, M_ROWS/128), 256>>>(
        xc1, D_INNER, W_x_b, D_INNER, nullptr, xd1, NK, NK, D_INNER);

    // 4) dt per branch: softplus(dt_lo @ W_dt^T + b_dt)  (M=4096, N=1536, K=48)
    gemm_tf32x3<1><<<dim3(D_INNER/128, M_ROWS/128), 256>>>(
        xd0, NK, W_dt,   DT_RANK, b_dt,   dt0, D_INNER, D_INNER, DT_RANK);
    gemm_tf32x3<1><<<dim3(D_INNER/128, M_ROWS/128), 256>>>(
        xd1, NK, W_dt_b, DT_RANK, b_dt_b, dt1, D_INNER, D_INNER, DT_RANK);

    // 5) selective scan, both branches
    scan_kernel<<<dim3(D_INNER/16, B_SZ, 2), 256>>>(A_log, A_b_log, Dp, Dp_b);

    // 6) combine with gate
    combine_kernel<<<(M_ROWS*D_INNER)/256, 256>>>();

    // 7) out-proj: (M=4096, N=768, K=1536)
    gemm_tf32x3<0><<<dim3(D_MODEL/128, M_ROWS/128), 256>>>(
        gb, D_INNER, W_out, D_INNER, nullptr, out, D_MODEL, D_MODEL, D_INNER);
}

// round 4
// speedup vs baseline: 1.5886x; 1.1381x over previous
#include <cuda_runtime.h>
#include <math.h>
#include <stdint.h>

#define B_SZ    2
#define L_SEQ   2048
#define D_MODEL 768
#define D_INNER 1536
#define D_STATE 16
#define DT_RANK 48
#define NK      (DT_RANK + 2*D_STATE)   /* 80 */
#define M_ROWS  (B_SZ*L_SEQ)            /* 4096 */

// ---------------- scratch (static device globals; no allocation) ----------------
__device__ float g_xz  [M_ROWS * 2 * D_INNER];
__device__ float g_xc  [2][M_ROWS * D_INNER];
__device__ float g_xd  [2][M_ROWS * NK];
__device__ float g_dt  [2][M_ROWS * D_INNER];
__device__ float g_y   [2][M_ROWS * D_INNER];
__device__ float g_gbuf[M_ROWS * D_INNER];

__device__ __forceinline__ float siluf(float x) {
    return x / (1.f + __expf(-x));
}

__device__ __forceinline__ void mma_tf32(float& c0, float& c1, float& c2, float& c3,
                                         uint32_t a0, uint32_t a1, uint32_t a2, uint32_t a3,
                                         uint32_t b0, uint32_t b1) {
    asm volatile("mma.sync.aligned.m16n8k8.row.col.f32.tf32.tf32.f32 "
                 "{%0,%1,%2,%3},{%4,%5,%6,%7},{%8,%9},{%0,%1,%2,%3};"
                 : "+f"(c0), "+f"(c1), "+f"(c2), "+f"(c3)
                 : "r"(a0), "r"(a1), "r"(a2), "r"(a3), "r"(b0), "r"(b1));
}

// hi/lo split WITHOUT cvt: hi = truncate-to-tf32 via mask (exact), lo = x - hi (exact FADD).
// MMA HW truncates register bits below tf32 mantissa, so no explicit rounding needed.
#define TF32_MASK 0xFFFFE000u

// =====================================================================
// 3xTF32 tensor-core NT GEMM: C[m,n] = act(sum_k A[m,k]*B[n,k] + bias[n])
// BN=128, BK=16, 8 warps: wm in {0,1} covers BM/2 rows, wn in {0..3} covers 32 cols.
// gridDim.z selects branch (A+=sA, B=B1, bias=bias1, C+=sC).
// Requires M % BM == 0, K % 16 == 0, lda/ldb % 4 == 0. N guarded.
// ACT: 0=none, 1=softplus(+bias).
// =====================================================================
#define SROW 20

template<int BM, int ACT>
__global__ void __launch_bounds__(256)
gemm_tf32x3(const float* __restrict__ A, int lda, long sA,
            const float* __restrict__ B0, const float* __restrict__ B1, int ldb,
            const float* __restrict__ bias0, const float* __restrict__ bias1,
            float* __restrict__ C, int ldc, long sC,
            int N, int K)
{
    const float* B = B0;
    const float* bias = bias0;
    if (blockIdx.z) { B = B1; bias = bias1; A += sA; C += sC; }

    __shared__ float As[2][BM][SROW];
    __shared__ float Bs[2][128][SROW];

    constexpr int ITI = BM / 32;            // i-tiles per warp
    constexpr int ALD = BM / 64;            // float4 A loads per thread (1 or 2)

    const int tid  = threadIdx.x;
    const int lane = tid & 31;
    const int g    = lane >> 2;
    const int tg   = lane & 3;
    const int warp = tid >> 5;
    const int wm   = warp & 1;
    const int wn   = warp >> 1;

    const int blockRow = blockIdx.y * BM;
    const int blockCol = blockIdx.x * 128;

    const int fq = tid & 3;
    const int fr = tid >> 2;

    float4 pa[2], pb[2];
    const int ktiles = K / 16;

    // ---- prefetch tile 0 ----
    {
        const float* Ap = A + (size_t)(blockRow + fr) * lda + fq * 4;
        pa[0] = *(const float4*)(Ap);
        if (ALD == 2) pa[1] = *(const float4*)(Ap + (size_t)64 * lda);
        int n0 = blockCol + fr, n1 = n0 + 64;
        pb[0] = (n0 < N) ? *(const float4*)(B + (size_t)n0 * ldb + fq * 4) : make_float4(0.f,0.f,0.f,0.f);
        pb[1] = (n1 < N) ? *(const float4*)(B + (size_t)n1 * ldb + fq * 4) : make_float4(0.f,0.f,0.f,0.f);
    }
    // store stage 0
    *(float4*)&As[0][fr][fq*4] = pa[0];
    if (ALD == 2) *(float4*)&As[0][fr + 64][fq*4] = pa[1];
    *(float4*)&Bs[0][fr     ][fq*4] = pb[0];
    *(float4*)&Bs[0][fr + 64][fq*4] = pb[1];
    __syncthreads();

    float acc[ITI][4][4];
    #pragma unroll
    for (int i = 0; i < ITI; ++i)
        #pragma unroll
        for (int j = 0; j < 4; ++j)
            #pragma unroll
            for (int r = 0; r < 4; ++r)
                acc[i][j][r] = 0.f;

    const int mwbase = wm * (BM/2);
    const int nwbase = wn * 32;

    for (int kt = 0; kt < ktiles; ++kt) {
        const int cur = kt & 1, nxt = cur ^ 1;
        const bool more = (kt + 1 < ktiles);

        // issue gmem loads for next tile (results consumed after compute)
        if (more) {
            int k0 = (kt + 1) * 16;
            const float* Ap = A + (size_t)(blockRow + fr) * lda + k0 + fq * 4;
            pa[0] = *(const float4*)(Ap);
            if (ALD == 2) pa[1] = *(const float4*)(Ap + (size_t)64 * lda);
            int n0 = blockCol + fr, n1 = n0 + 64;
            pb[0] = (n0 < N) ? *(const float4*)(B + (size_t)n0 * ldb + k0 + fq * 4) : make_float4(0.f,0.f,0.f,0.f);
            pb[1] = (n1 < N) ? *(const float4*)(B + (size_t)n1 * ldb + k0 + fq * 4) : make_float4(0.f,0.f,0.f,0.f);
        }

        // compute on current buffer: two k8 steps
        #pragma unroll
        for (int s = 0; s < 2; ++s) {
            const int kb = s * 8;
            uint32_t bh[4][2], bl[4][2];
            #pragma unroll
            for (int j = 0; j < 4; ++j) {
                float b0 = Bs[cur][nwbase + j*8 + g][kb + tg];
                float b1 = Bs[cur][nwbase + j*8 + g][kb + tg + 4];
                bh[j][0] = __float_as_uint(b0) & TF32_MASK;
                bl[j][0] = __float_as_uint(b0 - __uint_as_float(bh[j][0]));
                bh[j][1] = __float_as_uint(b1) & TF32_MASK;
                bl[j][1] = __float_as_uint(b1 - __uint_as_float(bh[j][1]));
            }
            #pragma unroll
            for (int i = 0; i < ITI; ++i) {
                const int mb = mwbase + i * 16;
                float a0 = As[cur][mb + g    ][kb + tg];
                float a1 = As[cur][mb + g + 8][kb + tg];
                float a2 = As[cur][mb + g    ][kb + tg + 4];
                float a3 = As[cur][mb + g + 8][kb + tg + 4];
                uint32_t ah0 = __float_as_uint(a0) & TF32_MASK;
                uint32_t ah1 = __float_as_uint(a1) & TF32_MASK;
                uint32_t ah2 = __float_as_uint(a2) & TF32_MASK;
                uint32_t ah3 = __float_as_uint(a3) & TF32_MASK;
                uint32_t al0 = __float_as_uint(a0 - __uint_as_float(ah0));
                uint32_t al1 = __float_as_uint(a1 - __uint_as_float(ah1));
                uint32_t al2 = __float_as_uint(a2 - __uint_as_float(ah2));
                uint32_t al3 = __float_as_uint(a3 - __uint_as_float(ah3));
                #pragma unroll
                for (int j = 0; j < 4; ++j) {
                    mma_tf32(acc[i][j][0], acc[i][j][1], acc[i][j][2], acc[i][j][3],
                             ah0, ah1, ah2, ah3, bh[j][0], bh[j][1]);
                    mma_tf32(acc[i][j][0], acc[i][j][1], acc[i][j][2], acc[i][j][3],
                             ah0, ah1, ah2, ah3, bl[j][0], bl[j][1]);
                    mma_tf32(acc[i][j][0], acc[i][j][1], acc[i][j][2], acc[i][j][3],
                             al0, al1, al2, al3, bh[j][0], bh[j][1]);
                }
            }
        }

        // store next tile into other buffer (safe: all warps left it at last sync)
        if (more) {
            *(float4*)&As[nxt][fr][fq*4] = pa[0];
            if (ALD == 2) *(float4*)&As[nxt][fr + 64][fq*4] = pa[1];
            *(float4*)&Bs[nxt][fr     ][fq*4] = pb[0];
            *(float4*)&Bs[nxt][fr + 64][fq*4] = pb[1];
        }
        __syncthreads();
    }

    // ---- epilogue ----
    #pragma unroll
    for (int i = 0; i < ITI; ++i) {
        int r0 = blockRow + mwbase + i*16 + g;
        int r1 = r0 + 8;
        #pragma unroll
        for (int j = 0; j < 4; ++j) {
            int c0 = blockCol + nwbase + j*8 + 2*tg;
            #pragma unroll
            for (int h = 0; h < 2; ++h) {
                int cc = c0 + h;
                if (cc < N) {
                    float v0 = acc[i][j][0 + h];
                    float v1 = acc[i][j][2 + h];
                    if (ACT == 1) {
                        float bv = bias[cc];
                        v0 += bv; v1 += bv;
                        v0 = (v0 > 20.f) ? v0 : log1pf(expf(v0));
                        v1 = (v1 > 20.f) ? v1 : log1pf(expf(v1));
                    }
                    C[(size_t)r0 * ldc + cc] = v0;
                    C[(size_t)r1 * ldc + cc] = v1;
                }
            }
        }
    }
}

// ---------------- depthwise causal conv (4 taps) + bias + silu, both branches ----------------
__global__ void conv_kernel(const float* __restrict__ cw_f, const float* __restrict__ cb_f,
                            const float* __restrict__ cw_b, const float* __restrict__ cb_b)
{
    int d = blockIdx.x*blockDim.x + threadIdx.x;
    int m = blockIdx.y;
    int b = m >> 11, t = m & (L_SEQ-1);

    float w0 = cw_f[d*4+0], w1 = cw_f[d*4+1], w2 = cw_f[d*4+2], w3 = cw_f[d*4+3];
    float v0 = cw_b[d*4+0], v1 = cw_b[d*4+1], v2 = cw_b[d*4+2], v3 = cw_b[d*4+3];

    const float* xcol = g_xz + d;
    size_t rowb = (size_t)(b*L_SEQ) * (2*D_INNER);

    float accf = cb_f[d];
    float accb = cb_b[d];
    if (t >= 3) accf += w0 * xcol[rowb + (size_t)(t-3)*(2*D_INNER)];
    if (t >= 2) accf += w1 * xcol[rowb + (size_t)(t-2)*(2*D_INNER)];
    if (t >= 1) accf += w2 * xcol[rowb + (size_t)(t-1)*(2*D_INNER)];
    accf += w3 * xcol[rowb + (size_t)t*(2*D_INNER)];
    if (t >= 3) accb += v0 * xcol[rowb + (size_t)(L_SEQ-1-(t-3))*(2*D_INNER)];
    if (t >= 2) accb += v1 * xcol[rowb + (size_t)(L_SEQ-1-(t-2))*(2*D_INNER)];
    if (t >= 1) accb += v2 * xcol[rowb + (size_t)(L_SEQ-1-(t-1))*(2*D_INNER)];
    accb += v3 * xcol[rowb + (size_t)(L_SEQ-1-t)*(2*D_INNER)];

    g_xc[0][(size_t)m*D_INNER + d] = siluf(accf);
    g_xc[1][(size_t)m*D_INNER + d] = siluf(accb);
}

// ---------------- selective scan, both branches via blockIdx.z ----------------
__global__ void scan_kernel(const float* __restrict__ Alog_f, const float* __restrict__ Alog_b,
                            const float* __restrict__ Dp_f,  const float* __restrict__ Dp_b)
{
    const int br = blockIdx.z;
    const float* __restrict__ dtbuf = br ? g_dt[1] : g_dt[0];
    const float* __restrict__ xcbuf = br ? g_xc[1] : g_xc[0];
    const float* __restrict__ xdbuf = br ? g_xd[1] : g_xd[0];
    float*       __restrict__ ybuf  = br ? g_y[1]  : g_y[0];
    const float* __restrict__ Alog  = br ? Alog_b : Alog_f;
    const float* __restrict__ Dpp   = br ? Dp_b   : Dp_f;

    const int tid  = threadIdx.x;
    const int lane = tid & 31;
    const int warp = tid >> 5;
    const int n    = lane & 15;
    const int dloc = warp*2 + (lane >> 4);
    const int d    = blockIdx.x*16 + dloc;
    const int b    = blockIdx.y;

    const float Acoef = -__expf(Alog[d*D_STATE + n]);
    const float Dv    = Dpp[d];

    const float* dtp = dtbuf + (size_t)b*L_SEQ*D_INNER + d;
    const float* xcp = xcbuf + (size_t)b*L_SEQ*D_INNER + d;
    const float* Bp  = xdbuf + (size_t)b*L_SEQ*NK + DT_RANK + n;
    const float* Cp  = Bp + D_STATE;

    float h = 0.f;
    for (int t = 0; t < L_SEQ; ++t) {
        float dt = __ldg(dtp + (size_t)t*D_INNER);
        float xv = __ldg(xcp + (size_t)t*D_INNER);
        float Bv = __ldg(Bp  + (size_t)t*NK);
        float Cv = __ldg(Cp  + (size_t)t*NK);

        float dA = __expf(dt * Acoef);
        h = dA*h + (dt*xv)*Bv;

        float p = h * Cv;
        p += __shfl_xor_sync(0xffffffffu, p, 8);
        p += __shfl_xor_sync(0xffffffffu, p, 4);
        p += __shfl_xor_sync(0xffffffffu, p, 2);
        p += __shfl_xor_sync(0xffffffffu, p, 1);

        if (n == 0) {
            int lout = br ? (L_SEQ - 1 - t) : t;
            ybuf[((size_t)b*L_SEQ + lout)*D_INNER + d] = p + Dv*xv;
        }
    }
}

// ---------------- combine: g = 0.5 * silu(z) * (y_f + y_b) ----------------
__global__ void combine_kernel()
{
    int idx = blockIdx.x*blockDim.x + threadIdx.x;
    int m = idx / D_INNER;
    int d = idx - m*D_INNER;
    float z = g_xz[(size_t)m*(2*D_INNER) + D_INNER + d];
    float s = siluf(z);
    g_gbuf[idx] = 0.5f * s * (g_y[0][idx] + g_y[1][idx]);
}

// ---------------- host ----------------
extern "C" void kernel_launch(void* const* d_in, const int* in_sizes, int n_in,
                              void* d_out, int out_size)
{
    const float* hs       = (const float*)d_in[0];
    const float* W_in     = (const float*)d_in[1];
    const float* conv_w   = (const float*)d_in[2];
    const float* conv_b   = (const float*)d_in[3];
    const float* conv_w_b = (const float*)d_in[4];
    const float* conv_b_b = (const float*)d_in[5];
    const float* W_x      = (const float*)d_in[6];
    const float* W_x_b    = (const float*)d_in[7];
    const float* W_dt     = (const float*)d_in[8];
    const float* b_dt     = (const float*)d_in[9];
    const float* W_dt_b   = (const float*)d_in[10];
    const float* b_dt_b   = (const float*)d_in[11];
    const float* A_log    = (const float*)d_in[12];
    const float* A_b_log  = (const float*)d_in[13];
    const float* Dp       = (const float*)d_in[14];
    const float* Dp_b     = (const float*)d_in[15];
    const float* W_out    = (const float*)d_in[16];
    float* out = (float*)d_out;

    static float *xz = nullptr, *xc = nullptr, *xd = nullptr, *dt = nullptr, *gb = nullptr;
    if (!xz) {
        cudaGetSymbolAddress((void**)&xz, g_xz);
        cudaGetSymbolAddress((void**)&xc, g_xc);
        cudaGetSymbolAddress((void**)&xd, g_xd);
        cudaGetSymbolAddress((void**)&dt, g_dt);
        cudaGetSymbolAddress((void**)&gb, g_gbuf);
    }
    const long sXC = (long)M_ROWS * D_INNER;
    const long sXD = (long)M_ROWS * NK;
    const long sDT = (long)M_ROWS * D_INNER;

    // 1) in-proj: (M=4096, N=3072, K=768)
    gemm_tf32x3<128,0><<<dim3(3072/128, M_ROWS/128, 1), 256>>>(
        hs, D_MODEL, 0, W_in, W_in, D_MODEL, nullptr, nullptr,
        xz, 2*D_INNER, 0, 2*D_INNER, D_MODEL);

    // 2) conv + silu (both branches)
    conv_kernel<<<dim3(D_INNER/256, M_ROWS), 256>>>(conv_w, conv_b, conv_w_b, conv_b_b);

    // 3) x_dbl both branches: (M=4096, N=80, K=1536), BM=64, grid.z=2
    gemm_tf32x3<64,0><<<dim3(1, M_ROWS/64, 2), 256>>>(
        xc, D_INNER, sXC, W_x, W_x_b, D_INNER, nullptr, nullptr,
        xd, NK, sXD, NK, D_INNER);

    // 4) dt both branches: softplus(dt_lo @ W_dt^T + b_dt)  (M=4096, N=1536, K=48)
    gemm_tf32x3<128,1><<<dim3(D_INNER/128, M_ROWS/128, 2), 256>>>(
        xd, NK, sXD, W_dt, W_dt_b, DT_RANK, b_dt, b_dt_b,
        dt, D_INNER, sDT, D_INNER, DT_RANK);

    // 5) selective scan, both branches
    scan_kernel<<<dim3(D_INNER/16, B_SZ, 2), 256>>>(A_log, A_b_log, Dp, Dp_b);

    // 6) combine with gate
    combine_kernel<<<(M_ROWS*D_INNER)/256, 256>>>();

    // 7) out-proj: (M=4096, N=768, K=1536)
    gemm_tf32x3<128,0><<<dim3(D_MODEL/128, M_ROWS/128, 1), 256>>>(
        gb, D_INNER, 0, W_out, W_out, D_INNER, nullptr, nullptr,
        out, D_MODEL, 0, D_MODEL, D_INNER);
}

// round 5
// speedup vs baseline: 1.6470x; 1.0368x over previous
#include <cuda_runtime.h>
#include <math.h>
#include <stdint.h>

#define B_SZ    2
#define L_SEQ   2048
#define D_MODEL 768
#define D_INNER 1536
#define D_STATE 16
#define DT_RANK 48
#define NK      (DT_RANK + 2*D_STATE)   /* 80 */
#define M_ROWS  (B_SZ*L_SEQ)            /* 4096 */

// ---------------- scratch (static device globals; no allocation) ----------------
__device__ float g_xz  [M_ROWS * 2 * D_INNER];
__device__ float g_xc  [2][M_ROWS * D_INNER];
__device__ float g_xd  [2][M_ROWS * NK];
__device__ float g_dt  [2][M_ROWS * D_INNER];
__device__ float g_y   [2][M_ROWS * D_INNER];
__device__ float g_gbuf[M_ROWS * D_INNER];

__device__ __forceinline__ float siluf(float x) {
    return x / (1.f + __expf(-x));
}

// fast softplus: max(v,0) + log(1+exp(-|v|)), MUFU-based
__device__ __forceinline__ float softplusf(float v) {
    return fmaxf(v, 0.f) + __logf(1.f + __expf(-fabsf(v)));
}

__device__ __forceinline__ void mma_tf32(float& c0, float& c1, float& c2, float& c3,
                                         uint32_t a0, uint32_t a1, uint32_t a2, uint32_t a3,
                                         uint32_t b0, uint32_t b1) {
    asm volatile("mma.sync.aligned.m16n8k8.row.col.f32.tf32.tf32.f32 "
                 "{%0,%1,%2,%3},{%4,%5,%6,%7},{%8,%9},{%0,%1,%2,%3};"
                 : "+f"(c0), "+f"(c1), "+f"(c2), "+f"(c3)
                 : "r"(a0), "r"(a1), "r"(a2), "r"(a3), "r"(b0), "r"(b1));
}

#define TF32_MASK 0xFFFFE000u

__device__ __forceinline__ uint32_t s2u(const void* p) {
    return (uint32_t)__cvta_generic_to_shared(p);
}
#define CP_A16(dst, src)        asm volatile("cp.async.cg.shared.global [%0],[%1],16;\n"::"r"(dst),"l"(src))
#define CP_A16P(dst, src, nb)   asm volatile("cp.async.cg.shared.global [%0],[%1],16,%2;\n"::"r"(dst),"l"(src),"r"(nb))
#define CP_COMMIT()             asm volatile("cp.async.commit_group;\n":::"memory")
#define CP_WAIT0()              asm volatile("cp.async.wait_group 0;\n":::"memory")

// =====================================================================
// 3xTF32 tensor-core NT GEMM with cp.async double buffering.
// C[m,n] = act(sum_k A[m,k]*B[n,k] (+ bias[n]))
// BN=128, BK=16, 8 warps: wm {0,1} x wn {0..3}, warp tile (BM/2)x32.
// gridDim.z selects branch. M % BM == 0, K % 16 == 0. N guarded (even).
// =====================================================================
#define SROW 20

template<int BM, int ACT>
__global__ void __launch_bounds__(256, 2)
gemm_tf32x3(const float* __restrict__ A, int lda, long sA,
            const float* __restrict__ B0, const float* __restrict__ B1, int ldb,
            const float* __restrict__ bias0, const float* __restrict__ bias1,
            float* __restrict__ C, int ldc, long sC,
            int N, int K)
{
    const float* B = B0;
    const float* bias = bias0;
    if (blockIdx.z) { B = B1; bias = bias1; A += sA; C += sC; }

    __shared__ float As[2][BM][SROW];
    __shared__ float Bs[2][128][SROW];

    constexpr int ITI = BM / 32;
    constexpr int ALD = BM / 64;

    const int tid  = threadIdx.x;
    const int lane = tid & 31;
    const int g    = lane >> 2;
    const int tg   = lane & 3;
    const int warp = tid >> 5;
    const int wm   = warp & 1;
    const int wn   = warp >> 1;

    const int blockRow = blockIdx.y * BM;
    const int blockCol = blockIdx.x * 128;

    const int fq = tid & 3;
    const int fr = tid >> 2;

    const int ktiles = K / 16;

    const int n0 = blockCol + fr, n1 = n0 + 64;
    const float* Arow  = A + (size_t)(blockRow + fr) * lda + fq * 4;
    const float* Brow0 = B + (size_t)(n0 < N ? n0 : 0) * ldb + fq * 4;
    const float* Brow1 = B + (size_t)(n1 < N ? n1 : 0) * ldb + fq * 4;
    const int nb0 = (n0 < N) ? 16 : 0;
    const int nb1 = (n1 < N) ? 16 : 0;

    // ---- issue tile 0 ----
    {
        CP_A16(s2u(&As[0][fr][fq*4]), Arow);
        if (ALD == 2) CP_A16(s2u(&As[0][fr+64][fq*4]), Arow + (size_t)64 * lda);
        CP_A16P(s2u(&Bs[0][fr   ][fq*4]), Brow0, nb0);
        CP_A16P(s2u(&Bs[0][fr+64][fq*4]), Brow1, nb1);
        CP_COMMIT();
    }

    float acc[ITI][4][4];
    #pragma unroll
    for (int i = 0; i < ITI; ++i)
        #pragma unroll
        for (int j = 0; j < 4; ++j)
            #pragma unroll
            for (int r = 0; r < 4; ++r)
                acc[i][j][r] = 0.f;

    const int mwbase = wm * (BM/2);
    const int nwbase = wn * 32;

    for (int kt = 0; kt < ktiles; ++kt) {
        const int cur = kt & 1, nxt = cur ^ 1;

        CP_WAIT0();
        __syncthreads();

        if (kt + 1 < ktiles) {
            int k0 = (kt + 1) * 16;
            CP_A16(s2u(&As[nxt][fr][fq*4]), Arow + k0);
            if (ALD == 2) CP_A16(s2u(&As[nxt][fr+64][fq*4]), Arow + (size_t)64 * lda + k0);
            CP_A16P(s2u(&Bs[nxt][fr   ][fq*4]), Brow0 + k0, nb0);
            CP_A16P(s2u(&Bs[nxt][fr+64][fq*4]), Brow1 + k0, nb1);
            CP_COMMIT();
        }

        #pragma unroll
        for (int s = 0; s < 2; ++s) {
            const int kb = s * 8;
            uint32_t bh[4][2], bl[4][2];
            #pragma unroll
            for (int j = 0; j < 4; ++j) {
                float b0 = Bs[cur][nwbase + j*8 + g][kb + tg];
                float b1 = Bs[cur][nwbase + j*8 + g][kb + tg + 4];
                bh[j][0] = __float_as_uint(b0) & TF32_MASK;
                bl[j][0] = __float_as_uint(b0 - __uint_as_float(bh[j][0]));
                bh[j][1] = __float_as_uint(b1) & TF32_MASK;
                bl[j][1] = __float_as_uint(b1 - __uint_as_float(bh[j][1]));
            }
            #pragma unroll
            for (int i = 0; i < ITI; ++i) {
                const int mb = mwbase + i * 16;
                float a0 = As[cur][mb + g    ][kb + tg];
                float a1 = As[cur][mb + g + 8][kb + tg];
                float a2 = As[cur][mb + g    ][kb + tg + 4];
                float a3 = As[cur][mb + g + 8][kb + tg + 4];
                uint32_t ah0 = __float_as_uint(a0) & TF32_MASK;
                uint32_t ah1 = __float_as_uint(a1) & TF32_MASK;
                uint32_t ah2 = __float_as_uint(a2) & TF32_MASK;
                uint32_t ah3 = __float_as_uint(a3) & TF32_MASK;
                uint32_t al0 = __float_as_uint(a0 - __uint_as_float(ah0));
                uint32_t al1 = __float_as_uint(a1 - __uint_as_float(ah1));
                uint32_t al2 = __float_as_uint(a2 - __uint_as_float(ah2));
                uint32_t al3 = __float_as_uint(a3 - __uint_as_float(ah3));
                #pragma unroll
                for (int j = 0; j < 4; ++j) {
                    mma_tf32(acc[i][j][0], acc[i][j][1], acc[i][j][2], acc[i][j][3],
                             ah0, ah1, ah2, ah3, bh[j][0], bh[j][1]);
                    mma_tf32(acc[i][j][0], acc[i][j][1], acc[i][j][2], acc[i][j][3],
                             ah0, ah1, ah2, ah3, bl[j][0], bl[j][1]);
                    mma_tf32(acc[i][j][0], acc[i][j][1], acc[i][j][2], acc[i][j][3],
                             al0, al1, al2, al3, bh[j][0], bh[j][1]);
                }
            }
        }
    }

    // ---- epilogue (paired float2 stores; N is even) ----
    #pragma unroll
    for (int i = 0; i < ITI; ++i) {
        int r0 = blockRow + mwbase + i*16 + g;
        int r1 = r0 + 8;
        #pragma unroll
        for (int j = 0; j < 4; ++j) {
            int c0 = blockCol + nwbase + j*8 + 2*tg;
            if (c0 < N) {
                float v00 = acc[i][j][0], v01 = acc[i][j][1];
                float v10 = acc[i][j][2], v11 = acc[i][j][3];
                if (ACT == 1) {
                    float bv0 = bias[c0], bv1 = bias[c0+1];
                    v00 = softplusf(v00 + bv0); v01 = softplusf(v01 + bv1);
                    v10 = softplusf(v10 + bv0); v11 = softplusf(v11 + bv1);
                }
                *(float2*)&C[(size_t)r0 * ldc + c0] = make_float2(v00, v01);
                *(float2*)&C[(size_t)r1 * ldc + c0] = make_float2(v10, v11);
            }
        }
    }
}

// ---------------- depthwise causal conv (4 taps) + bias + silu, both branches ----------------
__global__ void conv_kernel(const float* __restrict__ cw_f, const float* __restrict__ cb_f,
                            const float* __restrict__ cw_b, const float* __restrict__ cb_b)
{
    int d = blockIdx.x*blockDim.x + threadIdx.x;
    int m = blockIdx.y;
    int b = m >> 11, t = m & (L_SEQ-1);

    float w0 = cw_f[d*4+0], w1 = cw_f[d*4+1], w2 = cw_f[d*4+2], w3 = cw_f[d*4+3];
    float v0 = cw_b[d*4+0], v1 = cw_b[d*4+1], v2 = cw_b[d*4+2], v3 = cw_b[d*4+3];

    const float* xcol = g_xz + d;
    size_t rowb = (size_t)(b*L_SEQ) * (2*D_INNER);

    float accf = cb_f[d];
    float accb = cb_b[d];
    if (t >= 3) accf += w0 * xcol[rowb + (size_t)(t-3)*(2*D_INNER)];
    if (t >= 2) accf += w1 * xcol[rowb + (size_t)(t-2)*(2*D_INNER)];
    if (t >= 1) accf += w2 * xcol[rowb + (size_t)(t-1)*(2*D_INNER)];
    accf += w3 * xcol[rowb + (size_t)t*(2*D_INNER)];
    if (t >= 3) accb += v0 * xcol[rowb + (size_t)(L_SEQ-1-(t-3))*(2*D_INNER)];
    if (t >= 2) accb += v1 * xcol[rowb + (size_t)(L_SEQ-1-(t-2))*(2*D_INNER)];
    if (t >= 1) accb += v2 * xcol[rowb + (size_t)(L_SEQ-1-(t-1))*(2*D_INNER)];
    accb += v3 * xcol[rowb + (size_t)(L_SEQ-1-t)*(2*D_INNER)];

    g_xc[0][(size_t)m*D_INNER + d] = siluf(accf);
    g_xc[1][(size_t)m*D_INNER + d] = siluf(accb);
}

// ---------------- selective scan: 4 lanes/channel x 4 states/lane ----------------
// Block = 64 threads = 16 channels. grid = (D_INNER/16, B_SZ, 2).
__global__ void __launch_bounds__(64)
scan_kernel(const float* __restrict__ Alog_f, const float* __restrict__ Alog_b,
            const float* __restrict__ Dp_f,  const float* __restrict__ Dp_b)
{
    const int br = blockIdx.z;
    const float* __restrict__ dtbuf = br ? g_dt[1] : g_dt[0];
    const float* __restrict__ xcbuf = br ? g_xc[1] : g_xc[0];
    const float* __restrict__ xdbuf = br ? g_xd[1] : g_xd[0];
    float*       __restrict__ ybuf  = br ? g_y[1]  : g_y[0];
    const float* __restrict__ Alog  = br ? Alog_b : Alog_f;
    const float* __restrict__ Dpp   = br ? Dp_b   : Dp_f;

    const int tid  = threadIdx.x;
    const int s    = tid & 3;          // state group: states 4s..4s+3
    const int cloc = tid >> 2;         // 0..15
    const int d    = blockIdx.x*16 + cloc;
    const int b    = blockIdx.y;

    float Ac0 = -__expf(Alog[d*D_STATE + 4*s + 0]);
    float Ac1 = -__expf(Alog[d*D_STATE + 4*s + 1]);
    float Ac2 = -__expf(Alog[d*D_STATE + 4*s + 2]);
    float Ac3 = -__expf(Alog[d*D_STATE + 4*s + 3]);
    const float Dv = Dpp[d];

    const float* dtp = dtbuf + (size_t)b*L_SEQ*D_INNER + d;
    const float* xcp = xcbuf + (size_t)b*L_SEQ*D_INNER + d;
    const float4* Bp = (const float4*)(xdbuf + (size_t)b*L_SEQ*NK + DT_RANK + 4*s);
    const float4* Cp = (const float4*)(xdbuf + (size_t)b*L_SEQ*NK + DT_RANK + D_STATE + 4*s);
    const int rstride4 = NK / 4;   // 20 float4s per row

    float h0 = 0.f, h1 = 0.f, h2 = 0.f, h3 = 0.f;

    // prefetch t=0
    float  dt_c = __ldg(dtp);
    float  xv_c = __ldg(xcp);
    float4 B_c  = __ldg(Bp);
    float4 C_c  = __ldg(Cp);

    const long ystride = br ? -(long)D_INNER : (long)D_INNER;
    float* yp = ybuf + ((size_t)b*L_SEQ + (br ? (L_SEQ-1) : 0)) * D_INNER + d;

    for (int t = 0; t < L_SEQ; ++t) {
        float dt_n, xv_n; float4 B_n, C_n;
        if (t + 1 < L_SEQ) {
            dt_n = __ldg(dtp + (size_t)(t+1)*D_INNER);
            xv_n = __ldg(xcp + (size_t)(t+1)*D_INNER);
            B_n  = __ldg(Bp + (size_t)(t+1)*rstride4);
            C_n  = __ldg(Cp + (size_t)(t+1)*rstride4);
        }

        float dbx = dt_c * xv_c;
        h0 = __expf(dt_c * Ac0) * h0 + dbx * B_c.x;
        h1 = __expf(dt_c * Ac1) * h1 + dbx * B_c.y;
        h2 = __expf(dt_c * Ac2) * h2 + dbx * B_c.z;
        h3 = __expf(dt_c * Ac3) * h3 + dbx * B_c.w;

        float p = h0*C_c.x + h1*C_c.y + h2*C_c.z + h3*C_c.w;
        p += __shfl_xor_sync(0xffffffffu, p, 1);
        p += __shfl_xor_sync(0xffffffffu, p, 2);

        if (s == 0) *yp = p + Dv * xv_c;
        yp += ystride;

        dt_c = dt_n; xv_c = xv_n; B_c = B_n; C_c = C_n;
    }
}

// ---------------- combine: g = 0.5 * silu(z) * (y_f + y_b) ----------------
__global__ void combine_kernel()
{
    int idx = blockIdx.x*blockDim.x + threadIdx.x;
    int m = idx / D_INNER;
    int d = idx - m*D_INNER;
    float z = g_xz[(size_t)m*(2*D_INNER) + D_INNER + d];
    float s = siluf(z);
    g_gbuf[idx] = 0.5f * s * (g_y[0][idx] + g_y[1][idx]);
}

// ---------------- host ----------------
extern "C" void kernel_launch(void* const* d_in, const int* in_sizes, int n_in,
                              void* d_out, int out_size)
{
    const float* hs       = (const float*)d_in[0];
    const float* W_in     = (const float*)d_in[1];
    const float* conv_w   = (const float*)d_in[2];
    const float* conv_b   = (const float*)d_in[3];
    const float* conv_w_b = (const float*)d_in[4];
    const float* conv_b_b = (const float*)d_in[5];
    const float* W_x      = (const float*)d_in[6];
    const float* W_x_b    = (const float*)d_in[7];
    const float* W_dt     = (const float*)d_in[8];
    const float* b_dt     = (const float*)d_in[9];
    const float* W_dt_b   = (const float*)d_in[10];
    const float* b_dt_b   = (const float*)d_in[11];
    const float* A_log    = (const float*)d_in[12];
    const float* A_b_log  = (const float*)d_in[13];
    const float* Dp       = (const float*)d_in[14];
    const float* Dp_b     = (const float*)d_in[15];
    const float* W_out    = (const float*)d_in[16];
    float* out = (float*)d_out;

    static float *xz = nullptr, *xc = nullptr, *xd = nullptr, *dt = nullptr, *gb = nullptr;
    if (!xz) {
        cudaGetSymbolAddress((void**)&xz, g_xz);
        cudaGetSymbolAddress((void**)&xc, g_xc);
        cudaGetSymbolAddress((void**)&xd, g_xd);
        cudaGetSymbolAddress((void**)&dt, g_dt);
        cudaGetSymbolAddress((void**)&gb, g_gbuf);
    }
    const long sXC = (long)M_ROWS * D_INNER;
    const long sXD = (long)M_ROWS * NK;
    const long sDT = (long)M_ROWS * D_INNER;

    // 1) in-proj: (M=4096, N=3072, K=768)
    gemm_tf32x3<128,0><<<dim3(3072/128, M_ROWS/128, 1), 256>>>(
        hs, D_MODEL, 0, W_in, W_in, D_MODEL, nullptr, nullptr,
        xz, 2*D_INNER, 0, 2*D_INNER, D_MODEL);

    // 2) conv + silu (both branches)
    conv_kernel<<<dim3(D_INNER/256, M_ROWS), 256>>>(conv_w, conv_b, conv_w_b, conv_b_b);

    // 3) x_dbl both branches: (M=4096, N=80, K=1536), BM=64, grid.z=2
    gemm_tf32x3<64,0><<<dim3(1, M_ROWS/64, 2), 256>>>(
        xc, D_INNER, sXC, W_x, W_x_b, D_INNER, nullptr, nullptr,
        xd, NK, sXD, NK, D_INNER);

    // 4) dt both branches: softplus(dt_lo @ W_dt^T + b_dt)  (M=4096, N=1536, K=48)
    gemm_tf32x3<128,1><<<dim3(D_INNER/128, M_ROWS/128, 2), 256>>>(
        xd, NK, sXD, W_dt, W_dt_b, DT_RANK, b_dt, b_dt_b,
        dt, D_INNER, sDT, D_INNER, DT_RANK);

    // 5) selective scan, both branches
    scan_kernel<<<dim3(D_INNER/16, B_SZ, 2), 64>>>(A_log, A_b_log, Dp, Dp_b);

    // 6) combine with gate
    combine_kernel<<<(M_ROWS*D_INNER)/256, 256>>>();

    // 7) out-proj: (M=4096, N=768, K=1536)
    gemm_tf32x3<128,0><<<dim3(D_MODEL/128, M_ROWS/128, 1), 256>>>(
        gb, D_INNER, 0, W_out, W_out, D_INNER, nullptr, nullptr,
        out, D_MODEL, 0, D_MODEL, D_INNER);
}

// round 6
// speedup vs baseline: 1.9008x; 1.1541x over previous
#include <cuda_runtime.h>
#include <math.h>
#include <stdint.h>

#define B_SZ    2
#define L_SEQ   2048
#define D_MODEL 768
#define D_INNER 1536
#define D_STATE 16
#define DT_RANK 48
#define NK      (DT_RANK + 2*D_STATE)   /* 80 */
#define M_ROWS  (B_SZ*L_SEQ)            /* 4096 */

// ---------------- scratch (static device globals; no allocation) ----------------
__device__ float g_xz  [M_ROWS * 2 * D_INNER];
__device__ float g_xc  [2][M_ROWS * D_INNER];
__device__ float g_xd  [2][M_ROWS * NK];
__device__ float g_dt  [2][M_ROWS * D_INNER];
__device__ float g_y   [2][M_ROWS * D_INNER];
__device__ float g_gbuf[M_ROWS * D_INNER];

__device__ __forceinline__ float siluf(float x) {
    return x / (1.f + __expf(-x));
}
__device__ __forceinline__ float softplusf(float v) {
    return fmaxf(v, 0.f) + __logf(1.f + __expf(-fabsf(v)));
}

__device__ __forceinline__ void mma_bf16(float& c0, float& c1, float& c2, float& c3,
                                         uint32_t a0, uint32_t a1, uint32_t a2, uint32_t a3,
                                         uint32_t b0, uint32_t b1) {
    asm volatile("mma.sync.aligned.m16n8k16.row.col.f32.bf16.bf16.f32 "
                 "{%0,%1,%2,%3},{%4,%5,%6,%7},{%8,%9},{%0,%1,%2,%3};"
                 : "+f"(c0), "+f"(c1), "+f"(c2), "+f"(c3)
                 : "r"(a0), "r"(a1), "r"(a2), "r"(a3), "r"(b0), "r"(b1));
}

// pack two fp32 -> bf16x2 (lo half = x, hi half = y), RN
__device__ __forceinline__ uint32_t packbf(float x, float y) {
    uint32_t r;
    asm("cvt.rn.bf16x2.f32 %0, %1, %2;" : "=r"(r) : "f"(y), "f"(x));
    return r;
}
// hi/lo split of float4 along k: h0={k0,k1}, h1={k2,k3}; l* = residuals
__device__ __forceinline__ void split4(float4 v, uint32_t& h0, uint32_t& h1,
                                       uint32_t& l0, uint32_t& l1) {
    h0 = packbf(v.x, v.y);
    h1 = packbf(v.z, v.w);
    float hx = __uint_as_float(h0 << 16),  hy = __uint_as_float(h0 & 0xFFFF0000u);
    float hz = __uint_as_float(h1 << 16),  hw = __uint_as_float(h1 & 0xFFFF0000u);
    l0 = packbf(v.x - hx, v.y - hy);
    l1 = packbf(v.z - hz, v.w - hw);
}

// =====================================================================
// bf16x3 tensor-core NT GEMM: C[m,n] = act(sum_k A[m,k]*B[n,k] (+bias))
// BN=128, BK=16 (one m16n8k16 step per tile). 8 warps: wm{0,1} x wn{0..3},
// warp tile (BM/2)x32. Smem holds packed bf16x2 hi/lo tiles, XOR swizzle:
// k-pair c of row r stored at col (c+r)&7 (stride 8, conflict-free).
// gridDim.z selects branch. M%BM==0, K%16==0, N guarded (even).
// =====================================================================
template<int BM, int ACT>
__global__ void __launch_bounds__(256, 2)
gemm_bf16x3(const float* __restrict__ A, int lda, long sA,
            const float* __restrict__ B0, const float* __restrict__ B1, int ldb,
            const float* __restrict__ bias0, const float* __restrict__ bias1,
            float* __restrict__ C, int ldc, long sC,
            int N, int K)
{
    const float* B = B0;
    const float* bias = bias0;
    if (blockIdx.z) { B = B1; bias = bias1; A += sA; C += sC; }

    __shared__ uint32_t As_h[2][BM][8],  As_l[2][BM][8];
    __shared__ uint32_t Bs_h[2][128][8], Bs_l[2][128][8];

    constexpr int ITI = BM / 32;
    constexpr int ALD = BM / 64;

    const int tid  = threadIdx.x;
    const int lane = tid & 31;
    const int g    = lane >> 2;
    const int tg   = lane & 3;
    const int warp = tid >> 5;
    const int wm   = warp & 1;
    const int wn   = warp >> 1;

    const int blockRow = blockIdx.y * BM;
    const int blockCol = blockIdx.x * 128;

    const int fq = tid & 3;      // float4 index within k16
    const int fr = tid >> 2;     // row 0..63 (+64)

    const int ktiles = K / 16;

    const int n0 = blockCol + fr, n1 = n0 + 64;
    const float* Arow  = A + (size_t)(blockRow + fr) * lda + fq * 4;
    const float* Brow0 = B + (size_t)(n0 < N ? n0 : 0) * ldb + fq * 4;
    const float* Brow1 = B + (size_t)(n1 < N ? n1 : 0) * ldb + fq * 4;
    const bool   bok0 = (n0 < N), bok1 = (n1 < N);

    float4 pa[2], pb[2];
    // ---- prefetch tile 0 ----
    pa[0] = *(const float4*)(Arow);
    if (ALD == 2) pa[1] = *(const float4*)(Arow + (size_t)64 * lda);
    pb[0] = bok0 ? *(const float4*)(Brow0) : make_float4(0.f,0.f,0.f,0.f);
    pb[1] = bok1 ? *(const float4*)(Brow1) : make_float4(0.f,0.f,0.f,0.f);

    float acc[ITI][4][4];
    #pragma unroll
    for (int i = 0; i < ITI; ++i)
        #pragma unroll
        for (int j = 0; j < 4; ++j)
            #pragma unroll
            for (int r = 0; r < 4; ++r)
                acc[i][j][r] = 0.f;

    const int mwbase = wm * (BM/2);
    const int nwbase = wn * 32;
    const int c1 = (tg + g) & 7;        // swizzled col for k-pair tg   (rows ≡ g mod 8)
    const int c2 = (tg + g + 4) & 7;    // swizzled col for k-pair tg+4

    // swizzled store cols for filler
    const int sc0 = (2*fq + fr) & 7;
    const int sc1 = (2*fq + 1 + fr) & 7;

    for (int kt = 0; kt < ktiles; ++kt) {
        const int buf = kt & 1;

        // convert + store prefetched tile into smem[buf]
        {
            uint32_t h0,h1,l0,l1;
            split4(pa[0], h0,h1,l0,l1);
            As_h[buf][fr][sc0] = h0; As_h[buf][fr][sc1] = h1;
            As_l[buf][fr][sc0] = l0; As_l[buf][fr][sc1] = l1;
            if (ALD == 2) {
                split4(pa[1], h0,h1,l0,l1);
                As_h[buf][fr+64][sc0] = h0; As_h[buf][fr+64][sc1] = h1;
                As_l[buf][fr+64][sc0] = l0; As_l[buf][fr+64][sc1] = l1;
            }
            split4(pb[0], h0,h1,l0,l1);
            Bs_h[buf][fr][sc0] = h0; Bs_h[buf][fr][sc1] = h1;
            Bs_l[buf][fr][sc0] = l0; Bs_l[buf][fr][sc1] = l1;
            split4(pb[1], h0,h1,l0,l1);
            Bs_h[buf][fr+64][sc0] = h0; Bs_h[buf][fr+64][sc1] = h1;
            Bs_l[buf][fr+64][sc0] = l0; Bs_l[buf][fr+64][sc1] = l1;
        }
        __syncthreads();

        // prefetch next tile (latency hidden under compute)
        if (kt + 1 < ktiles) {
            int k0 = (kt + 1) * 16;
            pa[0] = *(const float4*)(Arow + k0);
            if (ALD == 2) pa[1] = *(const float4*)(Arow + (size_t)64 * lda + k0);
            pb[0] = bok0 ? *(const float4*)(Brow0 + k0) : make_float4(0.f,0.f,0.f,0.f);
            pb[1] = bok1 ? *(const float4*)(Brow1 + k0) : make_float4(0.f,0.f,0.f,0.f);
        }

        // B fragments (hi/lo)
        uint32_t bh0[4], bh1[4], bl0[4], bl1[4];
        #pragma unroll
        for (int j = 0; j < 4; ++j) {
            int rn = nwbase + j*8 + g;
            bh0[j] = Bs_h[buf][rn][c1]; bh1[j] = Bs_h[buf][rn][c2];
            bl0[j] = Bs_l[buf][rn][c1]; bl1[j] = Bs_l[buf][rn][c2];
        }
        #pragma unroll
        for (int i = 0; i < ITI; ++i) {
            int r0 = mwbase + i*16 + g, r1 = r0 + 8;
            uint32_t ah0 = As_h[buf][r0][c1], ah1 = As_h[buf][r1][c1];
            uint32_t ah2 = As_h[buf][r0][c2], ah3 = As_h[buf][r1][c2];
            uint32_t al0 = As_l[buf][r0][c1], al1 = As_l[buf][r1][c1];
            uint32_t al2 = As_l[buf][r0][c2], al3 = As_l[buf][r1][c2];
            #pragma unroll
            for (int j = 0; j < 4; ++j) {
                mma_bf16(acc[i][j][0], acc[i][j][1], acc[i][j][2], acc[i][j][3],
                         ah0, ah1, ah2, ah3, bh0[j], bh1[j]);
                mma_bf16(acc[i][j][0], acc[i][j][1], acc[i][j][2], acc[i][j][3],
                         ah0, ah1, ah2, ah3, bl0[j], bl1[j]);
                mma_bf16(acc[i][j][0], acc[i][j][1], acc[i][j][2], acc[i][j][3],
                         al0, al1, al2, al3, bh0[j], bh1[j]);
            }
        }
    }

    // ---- epilogue (paired float2 stores; N is even) ----
    #pragma unroll
    for (int i = 0; i < ITI; ++i) {
        int r0 = blockRow + mwbase + i*16 + g;
        int r1 = r0 + 8;
        #pragma unroll
        for (int j = 0; j < 4; ++j) {
            int c0 = blockCol + nwbase + j*8 + 2*tg;
            if (c0 < N) {
                float v00 = acc[i][j][0], v01 = acc[i][j][1];
                float v10 = acc[i][j][2], v11 = acc[i][j][3];
                if (ACT == 1) {
                    float bv0 = bias[c0], bv1 = bias[c0+1];
                    v00 = softplusf(v00 + bv0); v01 = softplusf(v01 + bv1);
                    v10 = softplusf(v10 + bv0); v11 = softplusf(v11 + bv1);
                }
                *(float2*)&C[(size_t)r0 * ldc + c0] = make_float2(v00, v01);
                *(float2*)&C[(size_t)r1 * ldc + c0] = make_float2(v10, v11);
            }
        }
    }
}

// ---------------- depthwise causal conv: 4 timesteps per thread ----------------
// grid (D_INNER/128, M_ROWS/4), block 128. Blocks never straddle batch boundary.
__global__ void conv_kernel(const float* __restrict__ cw_f, const float* __restrict__ cb_f,
                            const float* __restrict__ cw_b, const float* __restrict__ cb_b)
{
    int d  = blockIdx.x*128 + threadIdx.x;
    int m0 = blockIdx.y * 4;
    int b = m0 >> 11, t0 = m0 & (L_SEQ-1);

    float w0 = cw_f[d*4+0], w1 = cw_f[d*4+1], w2 = cw_f[d*4+2], w3 = cw_f[d*4+3];
    float v0 = cw_b[d*4+0], v1 = cw_b[d*4+1], v2 = cw_b[d*4+2], v3 = cw_b[d*4+3];
    float cbf = cb_f[d], cbb = cb_b[d];

    const float* xcol = g_xz + (size_t)(b*L_SEQ)*(2*D_INNER) + d;

    float xf[7], xb[7];
    #pragma unroll
    for (int k = 0; k < 7; ++k) {
        int u = t0 - 3 + k;
        xf[k] = (u >= 0) ? xcol[(size_t)u*(2*D_INNER)] : 0.f;
        xb[k] = (u >= 0) ? xcol[(size_t)(L_SEQ-1-u)*(2*D_INNER)] : 0.f;
    }

    float* o0 = &g_xc[0][(size_t)m0*D_INNER + d];
    float* o1 = &g_xc[1][(size_t)m0*D_INNER + d];
    #pragma unroll
    for (int q = 0; q < 4; ++q) {
        float af = cbf + w0*xf[q] + w1*xf[q+1] + w2*xf[q+2] + w3*xf[q+3];
        float ab = cbb + v0*xb[q] + v1*xb[q+1] + v2*xb[q+2] + v3*xb[q+3];
        o0[(size_t)q*D_INNER] = siluf(af);
        o1[(size_t)q*D_INNER] = siluf(ab);
    }
}

// ---------------- selective scan: 4 lanes/channel x 4 states/lane ----------------
__global__ void __launch_bounds__(64)
scan_kernel(const float* __restrict__ Alog_f, const float* __restrict__ Alog_b,
            const float* __restrict__ Dp_f,  const float* __restrict__ Dp_b)
{
    const int br = blockIdx.z;
    const float* __restrict__ dtbuf = br ? g_dt[1] : g_dt[0];
    const float* __restrict__ xcbuf = br ? g_xc[1] : g_xc[0];
    const float* __restrict__ xdbuf = br ? g_xd[1] : g_xd[0];
    float*       __restrict__ ybuf  = br ? g_y[1]  : g_y[0];
    const float* __restrict__ Alog  = br ? Alog_b : Alog_f;
    const float* __restrict__ Dpp   = br ? Dp_b   : Dp_f;

    const int tid  = threadIdx.x;
    const int s    = tid & 3;
    const int cloc = tid >> 2;
    const int d    = blockIdx.x*16 + cloc;
    const int b    = blockIdx.y;

    float Ac0 = -__expf(Alog[d*D_STATE + 4*s + 0]);
    float Ac1 = -__expf(Alog[d*D_STATE + 4*s + 1]);
    float Ac2 = -__expf(Alog[d*D_STATE + 4*s + 2]);
    float Ac3 = -__expf(Alog[d*D_STATE + 4*s + 3]);
    const float Dv = Dpp[d];

    const float* dtp = dtbuf + (size_t)b*L_SEQ*D_INNER + d;
    const float* xcp = xcbuf + (size_t)b*L_SEQ*D_INNER + d;
    const float4* Bp = (const float4*)(xdbuf + (size_t)b*L_SEQ*NK + DT_RANK + 4*s);
    const float4* Cp = (const float4*)(xdbuf + (size_t)b*L_SEQ*NK + DT_RANK + D_STATE + 4*s);
    const int rstride4 = NK / 4;

    float h0 = 0.f, h1 = 0.f, h2 = 0.f, h3 = 0.f;

    float  dt_c = __ldg(dtp);
    float  xv_c = __ldg(xcp);
    float4 B_c  = __ldg(Bp);
    float4 C_c  = __ldg(Cp);

    const long ystride = br ? -(long)D_INNER : (long)D_INNER;
    float* yp = ybuf + ((size_t)b*L_SEQ + (br ? (L_SEQ-1) : 0)) * D_INNER + d;

    for (int t = 0; t < L_SEQ; ++t) {
        float dt_n, xv_n; float4 B_n, C_n;
        if (t + 1 < L_SEQ) {
            dt_n = __ldg(dtp + (size_t)(t+1)*D_INNER);
            xv_n = __ldg(xcp + (size_t)(t+1)*D_INNER);
            B_n  = __ldg(Bp + (size_t)(t+1)*rstride4);
            C_n  = __ldg(Cp + (size_t)(t+1)*rstride4);
        }

        float dbx = dt_c * xv_c;
        h0 = __expf(dt_c * Ac0) * h0 + dbx * B_c.x;
        h1 = __expf(dt_c * Ac1) * h1 + dbx * B_c.y;
        h2 = __expf(dt_c * Ac2) * h2 + dbx * B_c.z;
        h3 = __expf(dt_c * Ac3) * h3 + dbx * B_c.w;

        float p = h0*C_c.x + h1*C_c.y + h2*C_c.z + h3*C_c.w;
        p += __shfl_xor_sync(0xffffffffu, p, 1);
        p += __shfl_xor_sync(0xffffffffu, p, 2);

        if (s == 0) *yp = p + Dv * xv_c;
        yp += ystride;

        dt_c = dt_n; xv_c = xv_n; B_c = B_n; C_c = C_n;
    }
}

// ---------------- combine: g = 0.5 * silu(z) * (y_f + y_b) ----------------
__global__ void combine_kernel()
{
    int idx = blockIdx.x*blockDim.x + threadIdx.x;
    int m = idx / D_INNER;
    int d = idx - m*D_INNER;
    float z = g_xz[(size_t)m*(2*D_INNER) + D_INNER + d];
    float s = siluf(z);
    g_gbuf[idx] = 0.5f * s * (g_y[0][idx] + g_y[1][idx]);
}

// ---------------- host ----------------
extern "C" void kernel_launch(void* const* d_in, const int* in_sizes, int n_in,
                              void* d_out, int out_size)
{
    const float* hs       = (const float*)d_in[0];
    const float* W_in     = (const float*)d_in[1];
    const float* conv_w   = (const float*)d_in[2];
    const float* conv_b   = (const float*)d_in[3];
    const float* conv_w_b = (const float*)d_in[4];
    const float* conv_b_b = (const float*)d_in[5];
    const float* W_x      = (const float*)d_in[6];
    const float* W_x_b    = (const float*)d_in[7];
    const float* W_dt     = (const float*)d_in[8];
    const float* b_dt     = (const float*)d_in[9];
    const float* W_dt_b   = (const float*)d_in[10];
    const float* b_dt_b   = (const float*)d_in[11];
    const float* A_log    = (const float*)d_in[12];
    const float* A_b_log  = (const float*)d_in[13];
    const float* Dp       = (const float*)d_in[14];
    const float* Dp_b     = (const float*)d_in[15];
    const float* W_out    = (const float*)d_in[16];
    float* out = (float*)d_out;

    static float *xz = nullptr, *xc = nullptr, *xd = nullptr, *dt = nullptr, *gb = nullptr;
    if (!xz) {
        cudaGetSymbolAddress((void**)&xz, g_xz);
        cudaGetSymbolAddress((void**)&xc, g_xc);
        cudaGetSymbolAddress((void**)&xd, g_xd);
        cudaGetSymbolAddress((void**)&dt, g_dt);
        cudaGetSymbolAddress((void**)&gb, g_gbuf);
    }
    const long sXC = (long)M_ROWS * D_INNER;
    const long sXD = (long)M_ROWS * NK;
    const long sDT = (long)M_ROWS * D_INNER;

    // 1) in-proj: (M=4096, N=3072, K=768)
    gemm_bf16x3<128,0><<<dim3(3072/128, M_ROWS/128, 1), 256>>>(
        hs, D_MODEL, 0, W_in, W_in, D_MODEL, nullptr, nullptr,
        xz, 2*D_INNER, 0, 2*D_INNER, D_MODEL);

    // 2) conv + silu (both branches)
    conv_kernel<<<dim3(D_INNER/128, M_ROWS/4), 128>>>(conv_w, conv_b, conv_w_b, conv_b_b);

    // 3) x_dbl both branches: (M=4096, N=80, K=1536), BM=64, grid.z=2
    gemm_bf16x3<64,0><<<dim3(1, M_ROWS/64, 2), 256>>>(
        xc, D_INNER, sXC, W_x, W_x_b, D_INNER, nullptr, nullptr,
        xd, NK, sXD, NK, D_INNER);

    // 4) dt both branches: softplus(dt_lo @ W_dt^T + b_dt)  (M=4096, N=1536, K=48)
    gemm_bf16x3<128,1><<<dim3(D_INNER/128, M_ROWS/128, 2), 256>>>(
        xd, NK, sXD, W_dt, W_dt_b, DT_RANK, b_dt, b_dt_b,
        dt, D_INNER, sDT, D_INNER, DT_RANK);

    // 5) selective scan, both branches
    scan_kernel<<<dim3(D_INNER/16, B_SZ, 2), 64>>>(A_log, A_b_log, Dp, Dp_b);

    // 6) combine with gate
    combine_kernel<<<(M_ROWS*D_INNER)/256, 256>>>();

    // 7) out-proj: (M=4096, N=768, K=1536)
    gemm_bf16x3<128,0><<<dim3(D_MODEL/128, M_ROWS/128, 1), 256>>>(
        gb, D_INNER, 0, W_out, W_out, D_INNER, nullptr, nullptr,
        out, D_MODEL, 0, D_MODEL, D_INNER);
}